// round 7
// baseline (speedup 1.0000x reference)
#include <cuda_runtime.h>
#include <cuda_bf16.h>

// CL4CTR loss on GB300 — single fused kernel, independent warps.
//   x:   [4096, 39] int32 field indices      (d_in[0])
//   emb: [3900000, 16] float32               (d_in[1])
//   out: scalar float32
//
// 1024 blocks x 256 threads = 8 warps = 4 samples per block; 2 warps/sample,
// but each warp is FULLY independent until the block epilogue: it loads its
// own indices (via register shuffles, no smem round-trip), gathers a private
// transposed tile, computes its own norms, and runs half of the 55 Gram tiles.
// The twin warp's duplicate gathers hit L2. Gram inner loop uses packed
// fp32x2 FMA (fma.rn.f32x2); per-pair division via __fdividef (MUFU.RCP).
// Last block (atomic counter) combines and re-zeroes all accumulators so the
// zero-invariant holds across graph replays.

#define F_FIELDS 39
#define FP 40            // padded rows
#define NGRP 10          // 4-row groups (float4 granules per k-row)
#define NWARPS 8
#define NTHREADS 256
#define NBLOCKS 1024
#define EPSV 1e-4f

__device__ float g_s[624];       // s[f][d]
__device__ float g_acc[2];       // [0]=sum(sq), [1]=uniform sum
__device__ unsigned g_count;     // arrival counter (returns to 0 each run)

#define TT(i,j,w) ((unsigned)((i) | ((j)<<8) | ((w)<<16)))
__constant__ unsigned c_tiles[64] = {
  TT(0,0,1),TT(0,1,2),TT(0,2,2),TT(0,3,2),TT(0,4,2),TT(0,5,2),TT(0,6,2),TT(0,7,2),TT(0,8,2),TT(0,9,2),
  TT(1,1,1),TT(1,2,2),TT(1,3,2),TT(1,4,2),TT(1,5,2),TT(1,6,2),TT(1,7,2),TT(1,8,2),TT(1,9,2),
  TT(2,2,1),TT(2,3,2),TT(2,4,2),TT(2,5,2),TT(2,6,2),TT(2,7,2),TT(2,8,2),TT(2,9,2),
  TT(3,3,1),TT(3,4,2),TT(3,5,2),
  TT(3,6,2),TT(3,7,2),TT(3,8,2),TT(3,9,2),
  TT(4,4,1),TT(4,5,2),TT(4,6,2),TT(4,7,2),TT(4,8,2),TT(4,9,2),
  TT(5,5,1),TT(5,6,2),TT(5,7,2),TT(5,8,2),TT(5,9,2),
  TT(6,6,1),TT(6,7,2),TT(6,8,2),TT(6,9,2),
  TT(7,7,1),TT(7,8,2),TT(7,9,2),
  TT(8,8,1),TT(8,9,2),
  TT(9,9,1),
  TT(0,0,0),TT(0,0,0),TT(0,0,0),TT(0,0,0),TT(0,0,0),TT(0,0,0),TT(0,0,0),TT(0,0,0),TT(0,0,0)
};

typedef unsigned long long ull;

__device__ __forceinline__ ull pk2(float x) {            // (x, x) packed
    ull r; asm("mov.b64 %0, {%1, %1};" : "=l"(r) : "f"(x)); return r;
}
__device__ __forceinline__ void upk(ull v, float& x, float& y) {
    asm("mov.b64 {%0, %1}, %2;" : "=f"(x), "=f"(y) : "l"(v));
}
__device__ __forceinline__ ull fma2(ull a, ull b, ull c) {
    ull d; asm("fma.rn.f32x2 %0, %1, %2, %3;" : "=l"(d) : "l"(a), "l"(b), "l"(c));
    return d;
}

__global__ void __launch_bounds__(NTHREADS, 5)
cl4_fused(const int* __restrict__ x, const float* __restrict__ emb,
          float* __restrict__ out) {
    __shared__ __align__(16) float s_xt[NWARPS][16 * FP]; // per-WARP tile [k][r]
    __shared__ float s_n[NWARPS][FP];
    __shared__ float s_red[NWARPS][2];
    __shared__ unsigned s_last;
    __shared__ float s_fin[NWARPS];

    const int wid  = threadIdx.x >> 5;       // 0..7
    const int lane = threadIdx.x & 31;
    const int sm   = wid >> 1;               // sample slot 0..3
    const int h    = wid & 1;                // which half of the tile set
    const int b    = blockIdx.x * 4 + sm;    // 1024*4 = 4096 samples
    const int* xr  = x + b * F_FIELDS;

    // ---- indices in registers (2 coalesced LDGs), offsets folded in
    int v0 = (lane < 39)      ? __ldg(&xr[lane]) + lane * 100000 : 0;
    int v1 = (lane < 7)       ? __ldg(&xr[32 + lane]) + (32 + lane) * 100000 : 0;

    float* tile = s_xt[wid];

    // ---- gather full 39x16 tile (156 float4), transpose into private smem.
    // Row index comes from a register shuffle — no smem round-trip, LDGs
    // issue back-to-back with high MLP.
    #pragma unroll
    for (int it = 0; it < 5; it++) {
        int i = it * 32 + lane;
        int r = i >> 2, c = i & 3;
        int row = (it < 4) ? __shfl_sync(0xffffffffu, v0, r & 31)
                           : __shfl_sync(0xffffffffu, v1, (r - 32) & 31);
        if (i < 156) {
            float4 v = *reinterpret_cast<const float4*>(emb + (size_t)row * 16 + c * 4);
            float* dst = &tile[c * 4 * FP + r];
            dst[0]      = v.x;
            dst[FP]     = v.y;
            dst[2 * FP] = v.z;
            dst[3 * FP] = v.w;
        }
    }
    if (lane < 16) tile[lane * FP + 39] = 0.0f;      // zero pad row
    __syncwarp();

    // ---- norms (2 rounds, private copy) + sum(sq)
    float sumsq = 0.0f;
    {
        float sq = 0.0f;
        #pragma unroll
        for (int k = 0; k < 16; k++) {
            float v = tile[k * FP + lane];
            sq = fmaf(v, v, sq);
        }
        s_n[wid][lane] = sqrtf(sq);
        sumsq += sq;
    }
    {
        int rr = lane + 32;
        if (rr < FP) {
            float sq = 0.0f;
            #pragma unroll
            for (int k = 0; k < 16; k++) {
                float v = tile[k * FP + rr];
                sq = fmaf(v, v, sq);
            }
            s_n[wid][rr] = sqrtf(sq);
            sumsq += sq;                              // pad row adds 0
        }
    }
    if (h) sumsq = 0.0f;                              // avoid double count
    __syncwarp();

    // ---- Gram: warp h handles tile entries c_tiles[32h + lane].
    // Packed fp32x2: accumulate over the i-dimension pairs (rows 4I+{0,1}
    // and 4I+{2,3}) — the loaded float4 halves ARE the packed multiplicands.
    float usum = 0.0f;
    {
        unsigned e = c_tiles[(h << 5) + lane];
        int I = e & 255, J = (e >> 8) & 255;
        float wgt = (float)(e >> 16);

        ull acc01[4], acc23[4];
        #pragma unroll
        for (int j = 0; j < 4; j++) { acc01[j] = 0ull; acc23[j] = 0ull; }

        #pragma unroll
        for (int k = 0; k < 16; k++) {
            const float* rowk = tile + k * FP;
            ulonglong2 av = *reinterpret_cast<const ulonglong2*>(rowk + 4 * I);
            float4 bv     = *reinterpret_cast<const float4*>(rowk + 4 * J);
            ull b0 = pk2(bv.x), b1 = pk2(bv.y), b2 = pk2(bv.z), b3 = pk2(bv.w);
            acc01[0] = fma2(av.x, b0, acc01[0]);  acc23[0] = fma2(av.y, b0, acc23[0]);
            acc01[1] = fma2(av.x, b1, acc01[1]);  acc23[1] = fma2(av.y, b1, acc23[1]);
            acc01[2] = fma2(av.x, b2, acc01[2]);  acc23[2] = fma2(av.y, b2, acc23[2]);
            acc01[3] = fma2(av.x, b3, acc01[3]);  acc23[3] = fma2(av.y, b3, acc23[3]);
        }

        float nf0 = s_n[wid][4 * I],     nf1 = s_n[wid][4 * I + 1];
        float nf2 = s_n[wid][4 * I + 2], nf3 = s_n[wid][4 * I + 3];

        float ts = 0.0f;
        #pragma unroll
        for (int j = 0; j < 4; j++) {
            float ng = s_n[wid][4 * J + j];
            float a0, a1, a2, a3;
            upk(acc01[j], a0, a1);
            upk(acc23[j], a2, a3);
            ts += __fdividef(a0, fmaf(nf0, ng, EPSV));
            ts += __fdividef(a1, fmaf(nf1, ng, EPSV));
            ts += __fdividef(a2, fmaf(nf2, ng, EPSV));
            ts += __fdividef(a3, fmaf(nf3, ng, EPSV));
        }
        usum = wgt * ts;
    }

    // ---- warp reductions
    #pragma unroll
    for (int o = 16; o; o >>= 1) {
        usum  += __shfl_xor_sync(0xffffffffu, usum, o);
        sumsq += __shfl_xor_sync(0xffffffffu, sumsq, o);
    }
    if (lane == 0) { s_red[wid][0] = sumsq; s_red[wid][1] = usum; }
    __syncthreads();   // ONLY block-wide sync in the main path

    // ---- block epilogue: s[39][16] partial (even-warp tiles) + scalars
    for (int e = threadIdx.x; e < 624; e += NTHREADS) {
        int f = e >> 4, k = e & 15;
        float v = 0.0f;
        #pragma unroll
        for (int ss = 0; ss < 4; ss++) v += s_xt[2 * ss][k * FP + f];
        atomicAdd(&g_s[e], v);
    }
    if (threadIdx.x == 0) {
        float a = 0.0f, u = 0.0f;
        #pragma unroll
        for (int ww = 0; ww < NWARPS; ww++) { a += s_red[ww][0]; u += s_red[ww][1]; }
        atomicAdd(&g_acc[0], a);
        atomicAdd(&g_acc[1], u);
    }

    // ---- last-block election
    __threadfence();
    __syncthreads();
    if (threadIdx.x == 0) s_last = atomicAdd(&g_count, 1u);
    __syncthreads();
    if (s_last != NBLOCKS - 1) return;

    // ---- final: sum(s^2), combine, write scalar, RE-ZERO accumulators
    float ssq = 0.0f;
    for (int e = threadIdx.x; e < 624; e += NTHREADS) {
        float v = g_s[e];
        ssq = fmaf(v, v, ssq);
        g_s[e] = 0.0f;                                // restore zero-invariant
    }
    #pragma unroll
    for (int o = 16; o; o >>= 1) ssq += __shfl_xor_sync(0xffffffffu, ssq, o);
    if (lane == 0) s_fin[wid] = ssq;
    __syncthreads();

    if (threadIdx.x == 0) {
        float st = 0.0f;
        #pragma unroll
        for (int ww = 0; ww < NWARPS; ww++) st += s_fin[ww];
        double sumsq_t = (double)g_acc[0];
        double usum_t  = (double)g_acc[1];
        double pair    = 4096.0 * sumsq_t - (double)st;
        double align   = pair / (8386560.0 * 39.0);        // n_pairs * F
        double uni     = usum_t / (4096.0 * 39.0 * 39.0);  // B * F * F
        out[0] = (float)((align + uni) * 0.01);            // * BETA
        g_acc[0] = 0.0f;
        g_acc[1] = 0.0f;
        g_count  = 0u;                                     // reset for next replay
    }
}

extern "C" void kernel_launch(void* const* d_in, const int* in_sizes, int n_in,
                              void* d_out, int out_size) {
    const int*   x   = (const int*)d_in[0];
    const float* emb = (const float*)d_in[1];
    cl4_fused<<<NBLOCKS, NTHREADS>>>(x, emb, (float*)d_out);
}

// round 8
// speedup vs baseline: 1.1753x; 1.1753x over previous
#include <cuda_runtime.h>
#include <cuda_bf16.h>

// CL4CTR loss on GB300 — single fused kernel, 1 warp = 1 sample, short path.
//   x:   [4096, 39] int32 field indices      (d_in[0])
//   emb: [3900000, 16] float32               (d_in[1])
//   out: scalar float32
//
// 512 blocks x 256 threads (8 warps = 8 samples). Per warp:
//   indices in registers (2 coalesced LDGs + shfl) -> 5 LDG.128 gather
//   row norms computed FROM THE GATHER REGISTERS (quad butterfly shfl),
//   transposed tile stored once to smem, then a packed-fp32x2 Gram over the
//   55+9pad triangle tiles (2 sequential reps of 32 lane-tiles), per-pair
//   __fdividef. Block partial of s[39][16] -> global REDG atomics; last block
//   combines, writes scalar, re-zeroes accumulators (zero-invariant across
//   graph replays; device globals zero-initialized at load).

#define F_FIELDS 39
#define FP 40            // padded rows
#define NGRP 10          // float4 granules per k-row
#define NWARPS 8
#define NTHREADS 256
#define NBLOCKS 512
#define EPSV 1e-4f

__device__ float g_s[624];       // s[f][d]
__device__ float g_acc[2];       // [0]=sum(sq), [1]=uniform sum
__device__ unsigned g_count;     // arrival counter (returns to 0 each run)

#define TT(i,j,w) ((unsigned)((i) | ((j)<<8) | ((w)<<16)))
__constant__ unsigned c_tiles[64] = {
  TT(0,0,1),TT(0,1,2),TT(0,2,2),TT(0,3,2),TT(0,4,2),TT(0,5,2),TT(0,6,2),TT(0,7,2),TT(0,8,2),TT(0,9,2),
  TT(1,1,1),TT(1,2,2),TT(1,3,2),TT(1,4,2),TT(1,5,2),TT(1,6,2),TT(1,7,2),TT(1,8,2),TT(1,9,2),
  TT(2,2,1),TT(2,3,2),TT(2,4,2),TT(2,5,2),TT(2,6,2),TT(2,7,2),TT(2,8,2),TT(2,9,2),
  TT(3,3,1),TT(3,4,2),TT(3,5,2),TT(3,6,2),TT(3,7,2),TT(3,8,2),TT(3,9,2),
  TT(4,4,1),TT(4,5,2),TT(4,6,2),TT(4,7,2),TT(4,8,2),TT(4,9,2),
  TT(5,5,1),TT(5,6,2),TT(5,7,2),TT(5,8,2),TT(5,9,2),
  TT(6,6,1),TT(6,7,2),TT(6,8,2),TT(6,9,2),
  TT(7,7,1),TT(7,8,2),TT(7,9,2),
  TT(8,8,1),TT(8,9,2),
  TT(9,9,1),
  TT(0,0,0),TT(0,0,0),TT(0,0,0),TT(0,0,0),TT(0,0,0),TT(0,0,0),TT(0,0,0),TT(0,0,0),TT(0,0,0)
};

typedef unsigned long long ull;

__device__ __forceinline__ ull pk2(float x) {            // (x, x) packed
    ull r; asm("mov.b64 %0, {%1, %1};" : "=l"(r) : "f"(x)); return r;
}
__device__ __forceinline__ void upk(ull v, float& x, float& y) {
    asm("mov.b64 {%0, %1}, %2;" : "=f"(x), "=f"(y) : "l"(v));
}
__device__ __forceinline__ ull fma2(ull a, ull b, ull c) {
    ull d; asm("fma.rn.f32x2 %0, %1, %2, %3;" : "=l"(d) : "l"(a), "l"(b), "l"(c));
    return d;
}

__global__ void __launch_bounds__(NTHREADS)
cl4_fused(const int* __restrict__ x, const float* __restrict__ emb,
          float* __restrict__ out) {
    __shared__ __align__(16) float s_xt[NWARPS][16 * FP]; // tile [k][r] per warp
    __shared__ float s_n[NWARPS][FP];
    __shared__ float s_red[NWARPS][2];
    __shared__ unsigned s_last;
    __shared__ float s_fin[NWARPS];

    const int wid  = threadIdx.x >> 5;       // 0..7
    const int lane = threadIdx.x & 31;
    const int b    = blockIdx.x * NWARPS + wid;  // 512*8 = 4096 samples
    const int* xr  = x + b * F_FIELDS;

    // ---- indices in registers (2 coalesced LDGs), field offsets folded in
    int v0 = __ldg(&xr[lane]) + lane * 100000;                     // rows 0..31
    int v1 = (lane < 7) ? __ldg(&xr[32 + lane]) + (32 + lane) * 100000 : 0;

    float* tile = s_xt[wid];

    // ---- gather all 156 float4 chunks into registers (max MLP)
    float4 g[5];
    #pragma unroll
    for (int it = 0; it < 5; it++) {
        int i = it * 32 + lane;
        int r = i >> 2;
        int row = (it < 4) ? __shfl_sync(0xffffffffu, v0, r)
                           : __shfl_sync(0xffffffffu, v1, r - 32);
        if (i < 156) {
            int c = i & 3;
            g[it] = *reinterpret_cast<const float4*>(emb + (size_t)row * 16 + c * 4);
        } else {
            g[it] = make_float4(0.f, 0.f, 0.f, 0.f);
        }
    }

    // ---- norms from registers + transposed tile store + sum(sq)
    float sumsq = 0.0f;
    #pragma unroll
    for (int it = 0; it < 5; it++) {
        int i = it * 32 + lane;
        int r = i >> 2, c = i & 3;
        float4 v = g[it];
        float sqp = v.x * v.x;
        sqp = fmaf(v.y, v.y, sqp);
        sqp = fmaf(v.z, v.z, sqp);
        sqp = fmaf(v.w, v.w, sqp);
        sumsq += sqp;                                    // own-chunk partial
        // quad butterfly -> full row sq in all 4 lanes of the quad
        float sr = sqp;
        sr += __shfl_xor_sync(0xffffffffu, sr, 1);
        sr += __shfl_xor_sync(0xffffffffu, sr, 2);
        if (i < 156) {
            if (c == 0) s_n[wid][r] = sqrtf(sr);
            float* dst = &tile[c * 4 * FP + r];
            dst[0]      = v.x;
            dst[FP]     = v.y;
            dst[2 * FP] = v.z;
            dst[3 * FP] = v.w;
        }
    }
    if (lane < 16) tile[lane * FP + 39] = 0.0f;          // zero pad row
    if (lane == 16) s_n[wid][39] = 0.0f;
    __syncwarp();

    // ---- Gram: 2 sequential reps of 32 lane-tiles, packed fp32x2 over j.
    // bv float4 read directly as ulonglong2 = natively packed (b0,b1),(b2,b3).
    float usum = 0.0f;
    #pragma unroll
    for (int rep = 0; rep < 2; rep++) {
        unsigned e = c_tiles[(rep << 5) + lane];
        int I = e & 255, J = (e >> 8) & 255;
        float wgt = (float)(e >> 16);

        ull acc[4][2];
        #pragma unroll
        for (int i = 0; i < 4; i++) { acc[i][0] = 0ull; acc[i][1] = 0ull; }

        #pragma unroll
        for (int k = 0; k < 16; k++) {
            const float* rowk = tile + k * FP;
            float4     av = *reinterpret_cast<const float4*>(rowk + 4 * I);
            ulonglong2 bp = *reinterpret_cast<const ulonglong2*>(rowk + 4 * J);
            ull a0 = pk2(av.x), a1 = pk2(av.y), a2 = pk2(av.z), a3 = pk2(av.w);
            acc[0][0] = fma2(a0, bp.x, acc[0][0]);  acc[0][1] = fma2(a0, bp.y, acc[0][1]);
            acc[1][0] = fma2(a1, bp.x, acc[1][0]);  acc[1][1] = fma2(a1, bp.y, acc[1][1]);
            acc[2][0] = fma2(a2, bp.x, acc[2][0]);  acc[2][1] = fma2(a2, bp.y, acc[2][1]);
            acc[3][0] = fma2(a3, bp.x, acc[3][0]);  acc[3][1] = fma2(a3, bp.y, acc[3][1]);
        }

        float nf[4], ng[4];
        #pragma unroll
        for (int i = 0; i < 4; i++) {
            nf[i] = s_n[wid][4 * I + i];
            ng[i] = s_n[wid][4 * J + i];
        }

        float ts = 0.0f;
        #pragma unroll
        for (int i = 0; i < 4; i++) {
            float d0, d1, d2, d3;
            upk(acc[i][0], d0, d1);
            upk(acc[i][1], d2, d3);
            ts += __fdividef(d0, fmaf(nf[i], ng[0], EPSV));
            ts += __fdividef(d1, fmaf(nf[i], ng[1], EPSV));
            ts += __fdividef(d2, fmaf(nf[i], ng[2], EPSV));
            ts += __fdividef(d3, fmaf(nf[i], ng[3], EPSV));
        }
        usum = fmaf(wgt, ts, usum);
    }

    // ---- warp reductions
    #pragma unroll
    for (int o = 16; o; o >>= 1) {
        usum  += __shfl_xor_sync(0xffffffffu, usum, o);
        sumsq += __shfl_xor_sync(0xffffffffu, sumsq, o);
    }
    if (lane == 0) { s_red[wid][0] = sumsq; s_red[wid][1] = usum; }
    __syncthreads();   // only block-wide sync in the main path

    // ---- block-level s[39][16] partial + scalar partials -> global atomics
    for (int e = threadIdx.x; e < 624; e += NTHREADS) {
        int f = e >> 4, k = e & 15;
        float v = 0.0f;
        #pragma unroll
        for (int ww = 0; ww < NWARPS; ww++) v += s_xt[ww][k * FP + f];
        atomicAdd(&g_s[e], v);
    }
    if (threadIdx.x == 0) {
        float a = 0.0f, u = 0.0f;
        #pragma unroll
        for (int ww = 0; ww < NWARPS; ww++) { a += s_red[ww][0]; u += s_red[ww][1]; }
        atomicAdd(&g_acc[0], a);
        atomicAdd(&g_acc[1], u);
    }

    // ---- last-block election
    __threadfence();
    __syncthreads();
    if (threadIdx.x == 0) s_last = atomicAdd(&g_count, 1u);
    __syncthreads();
    if (s_last != NBLOCKS - 1) return;

    // ---- final: sum(s^2), combine, write scalar, RE-ZERO accumulators
    float ssq = 0.0f;
    for (int e = threadIdx.x; e < 624; e += NTHREADS) {
        float v = g_s[e];
        ssq = fmaf(v, v, ssq);
        g_s[e] = 0.0f;                                // restore zero-invariant
    }
    #pragma unroll
    for (int o = 16; o; o >>= 1) ssq += __shfl_xor_sync(0xffffffffu, ssq, o);
    if (lane == 0) s_fin[wid] = ssq;
    __syncthreads();

    if (threadIdx.x == 0) {
        float st = 0.0f;
        #pragma unroll
        for (int ww = 0; ww < NWARPS; ww++) st += s_fin[ww];
        double sumsq_t = (double)g_acc[0];
        double usum_t  = (double)g_acc[1];
        double pair    = 4096.0 * sumsq_t - (double)st;
        double align   = pair / (8386560.0 * 39.0);        // n_pairs * F
        double uni     = usum_t / (4096.0 * 39.0 * 39.0);  // B * F * F
        out[0] = (float)((align + uni) * 0.01);            // * BETA
        g_acc[0] = 0.0f;
        g_acc[1] = 0.0f;
        g_count  = 0u;                                     // reset for next replay
    }
}

extern "C" void kernel_launch(void* const* d_in, const int* in_sizes, int n_in,
                              void* d_out, int out_size) {
    const int*   x   = (const int*)d_in[0];
    const float* emb = (const float*)d_in[1];
    cl4_fused<<<NBLOCKS, NTHREADS>>>(x, emb, (float*)d_out);
}

// round 9
// speedup vs baseline: 1.3024x; 1.1081x over previous
#include <cuda_runtime.h>
#include <cuda_bf16.h>

// CL4CTR loss on GB300 — fused kernel, 2 samples per warp, pipelined gathers.
//   x:   [4096, 39] int32 field indices      (d_in[0])
//   emb: [3900000, 16] float32               (d_in[1])
//   out: scalar float32
//
// 256 blocks x 256 threads (8 warps); each warp processes samples b and b+8.
// All idx LDGs, then all 10 gather LDG.128s issue back-to-back (one DRAM
// round-trip covers both samples); sample A is processed (register norms,
// tile store, packed-fp32x2 Gram, __fdividef epilogue) while B's loads land.
// Block partial of s[39][16] over 16 tiles -> global atomics; last block
// combines, writes the scalar, and re-zeroes accumulators (zero-invariant
// across graph replays).

#define F_FIELDS 39
#define FP 40            // padded rows
#define NWARPS 8
#define NSAMP 16         // samples per block
#define NTHREADS 256
#define NBLOCKS 256
#define EPSV 1e-4f

__device__ float g_s[624];       // s[f][d]
__device__ float g_acc[2];       // [0]=sum(sq), [1]=uniform sum
__device__ unsigned g_count;     // arrival counter (returns to 0 each run)

#define TT(i,j,w) ((unsigned)((i) | ((j)<<8) | ((w)<<16)))
__constant__ unsigned c_tiles[64] = {
  TT(0,0,1),TT(0,1,2),TT(0,2,2),TT(0,3,2),TT(0,4,2),TT(0,5,2),TT(0,6,2),TT(0,7,2),TT(0,8,2),TT(0,9,2),
  TT(1,1,1),TT(1,2,2),TT(1,3,2),TT(1,4,2),TT(1,5,2),TT(1,6,2),TT(1,7,2),TT(1,8,2),TT(1,9,2),
  TT(2,2,1),TT(2,3,2),TT(2,4,2),TT(2,5,2),TT(2,6,2),TT(2,7,2),TT(2,8,2),TT(2,9,2),
  TT(3,3,1),TT(3,4,2),TT(3,5,2),TT(3,6,2),TT(3,7,2),TT(3,8,2),TT(3,9,2),
  TT(4,4,1),TT(4,5,2),TT(4,6,2),TT(4,7,2),TT(4,8,2),TT(4,9,2),
  TT(5,5,1),TT(5,6,2),TT(5,7,2),TT(5,8,2),TT(5,9,2),
  TT(6,6,1),TT(6,7,2),TT(6,8,2),TT(6,9,2),
  TT(7,7,1),TT(7,8,2),TT(7,9,2),
  TT(8,8,1),TT(8,9,2),
  TT(9,9,1),
  TT(0,0,0),TT(0,0,0),TT(0,0,0),TT(0,0,0),TT(0,0,0),TT(0,0,0),TT(0,0,0),TT(0,0,0),TT(0,0,0)
};

typedef unsigned long long ull;

__device__ __forceinline__ ull pk2(float x) {            // (x, x) packed
    ull r; asm("mov.b64 %0, {%1, %1};" : "=l"(r) : "f"(x)); return r;
}
__device__ __forceinline__ void upk(ull v, float& x, float& y) {
    asm("mov.b64 {%0, %1}, %2;" : "=f"(x), "=f"(y) : "l"(v));
}
__device__ __forceinline__ ull fma2(ull a, ull b, ull c) {
    ull d; asm("fma.rn.f32x2 %0, %1, %2, %3;" : "=l"(d) : "l"(a), "l"(b), "l"(c));
    return d;
}

// norms from gather registers (quad butterfly), transposed tile store, sum(sq)
__device__ __forceinline__ float store_norms(const float4* g, float* tile,
                                             float* nr, int lane) {
    float sumsq = 0.0f;
    #pragma unroll
    for (int it = 0; it < 5; it++) {
        int i = it * 32 + lane;
        int r = i >> 2, c = i & 3;
        float4 v = g[it];
        float sqp = fmaf(v.x, v.x, fmaf(v.y, v.y, fmaf(v.z, v.z, v.w * v.w)));
        sumsq += sqp;                                  // i>=156 chunks are zero
        float sr = sqp;
        sr += __shfl_xor_sync(0xffffffffu, sr, 1);
        sr += __shfl_xor_sync(0xffffffffu, sr, 2);
        if (i < 156) {
            if (c == 0) nr[r] = sqrtf(sr);
            float* dst = &tile[c * 4 * FP + r];
            dst[0]      = v.x;
            dst[FP]     = v.y;
            dst[2 * FP] = v.z;
            dst[3 * FP] = v.w;
        }
    }
    if (lane < 16) tile[lane * FP + 39] = 0.0f;        // zero pad row
    if (lane == 16) nr[39] = 0.0f;
    return sumsq;
}

// packed-fp32x2 Gram over the 55+9pad triangle tiles (both 32-lane reps)
__device__ __forceinline__ float gram_full(const float* tile, const float* nr,
                                           int lane) {
    float usum = 0.0f;
    #pragma unroll
    for (int rep = 0; rep < 2; rep++) {
        unsigned e = c_tiles[(rep << 5) + lane];
        int I = e & 255, J = (e >> 8) & 255;
        float wgt = (float)(e >> 16);

        ull acc[4][2];
        #pragma unroll
        for (int i = 0; i < 4; i++) { acc[i][0] = 0ull; acc[i][1] = 0ull; }

        #pragma unroll
        for (int k = 0; k < 16; k++) {
            const float* rowk = tile + k * FP;
            float4     av = *reinterpret_cast<const float4*>(rowk + 4 * I);
            ulonglong2 bp = *reinterpret_cast<const ulonglong2*>(rowk + 4 * J);
            ull a0 = pk2(av.x), a1 = pk2(av.y), a2 = pk2(av.z), a3 = pk2(av.w);
            acc[0][0] = fma2(a0, bp.x, acc[0][0]);  acc[0][1] = fma2(a0, bp.y, acc[0][1]);
            acc[1][0] = fma2(a1, bp.x, acc[1][0]);  acc[1][1] = fma2(a1, bp.y, acc[1][1]);
            acc[2][0] = fma2(a2, bp.x, acc[2][0]);  acc[2][1] = fma2(a2, bp.y, acc[2][1]);
            acc[3][0] = fma2(a3, bp.x, acc[3][0]);  acc[3][1] = fma2(a3, bp.y, acc[3][1]);
        }

        float nf[4], ng[4];
        #pragma unroll
        for (int i = 0; i < 4; i++) {
            nf[i] = nr[4 * I + i];
            ng[i] = nr[4 * J + i];
        }

        float ts = 0.0f;
        #pragma unroll
        for (int i = 0; i < 4; i++) {
            float d0, d1, d2, d3;
            upk(acc[i][0], d0, d1);
            upk(acc[i][1], d2, d3);
            ts += __fdividef(d0, fmaf(nf[i], ng[0], EPSV));
            ts += __fdividef(d1, fmaf(nf[i], ng[1], EPSV));
            ts += __fdividef(d2, fmaf(nf[i], ng[2], EPSV));
            ts += __fdividef(d3, fmaf(nf[i], ng[3], EPSV));
        }
        usum = fmaf(wgt, ts, usum);
    }
    return usum;
}

__global__ void __launch_bounds__(NTHREADS, 2)
cl4_fused(const int* __restrict__ x, const float* __restrict__ emb,
          float* __restrict__ out) {
    __shared__ __align__(16) float s_xt[NSAMP][16 * FP]; // tile [k][r] per sample
    __shared__ float s_n[NSAMP][FP];
    __shared__ float s_red[NWARPS][2];
    __shared__ unsigned s_last;
    __shared__ float s_fin[NWARPS];

    const int wid  = threadIdx.x >> 5;         // 0..7
    const int lane = threadIdx.x & 31;
    const int bA   = blockIdx.x * NSAMP + wid; // 256*16 = 4096 samples
    const int bB   = bA + NWARPS;
    const int* xrA = x + bA * F_FIELDS;
    const int* xrB = x + bB * F_FIELDS;

    // ---- all four idx LDGs up front (coalesced), field offsets folded in
    int a0 = __ldg(&xrA[lane]) + lane * 100000;
    int a1 = (lane < 7) ? __ldg(&xrA[32 + lane]) + (32 + lane) * 100000 : 0;
    int b0 = __ldg(&xrB[lane]) + lane * 100000;
    int b1 = (lane < 7) ? __ldg(&xrB[32 + lane]) + (32 + lane) * 100000 : 0;

    // ---- 10 gather LDG.128s back-to-back: one DRAM round-trip, both samples
    float4 gA[5], gB[5];
    #pragma unroll
    for (int it = 0; it < 5; it++) {
        int i = it * 32 + lane;
        int r = i >> 2, c = i & 3;
        int row = (it < 4) ? __shfl_sync(0xffffffffu, a0, r)
                           : __shfl_sync(0xffffffffu, a1, r - 32);
        gA[it] = (i < 156)
            ? *reinterpret_cast<const float4*>(emb + (size_t)row * 16 + c * 4)
            : make_float4(0.f, 0.f, 0.f, 0.f);
    }
    #pragma unroll
    for (int it = 0; it < 5; it++) {
        int i = it * 32 + lane;
        int r = i >> 2, c = i & 3;
        int row = (it < 4) ? __shfl_sync(0xffffffffu, b0, r)
                           : __shfl_sync(0xffffffffu, b1, r - 32);
        gB[it] = (i < 156)
            ? *reinterpret_cast<const float4*>(emb + (size_t)row * 16 + c * 4)
            : make_float4(0.f, 0.f, 0.f, 0.f);
    }

    float* tileA = s_xt[wid];
    float* tileB = s_xt[wid + NWARPS];

    // ---- process A while B's gathers are still in flight
    float sumsq = store_norms(gA, tileA, s_n[wid], lane);
    __syncwarp();
    float usum  = gram_full(tileA, s_n[wid], lane);

    // ---- process B (loads have long since landed)
    sumsq += store_norms(gB, tileB, s_n[wid + NWARPS], lane);
    __syncwarp();
    usum  += gram_full(tileB, s_n[wid + NWARPS], lane);

    // ---- warp reductions
    #pragma unroll
    for (int o = 16; o; o >>= 1) {
        usum  += __shfl_xor_sync(0xffffffffu, usum, o);
        sumsq += __shfl_xor_sync(0xffffffffu, sumsq, o);
    }
    if (lane == 0) { s_red[wid][0] = sumsq; s_red[wid][1] = usum; }
    __syncthreads();   // only block-wide sync in the main path

    // ---- block-level s[39][16] partial over 16 tiles + scalars -> atomics
    for (int e = threadIdx.x; e < 624; e += NTHREADS) {
        int f = e >> 4, k = e & 15;
        float v = 0.0f;
        #pragma unroll
        for (int ss = 0; ss < NSAMP; ss++) v += s_xt[ss][k * FP + f];
        atomicAdd(&g_s[e], v);
    }
    if (threadIdx.x == 0) {
        float a = 0.0f, u = 0.0f;
        #pragma unroll
        for (int ww = 0; ww < NWARPS; ww++) { a += s_red[ww][0]; u += s_red[ww][1]; }
        atomicAdd(&g_acc[0], a);
        atomicAdd(&g_acc[1], u);
    }

    // ---- last-block election
    __threadfence();
    __syncthreads();
    if (threadIdx.x == 0) s_last = atomicAdd(&g_count, 1u);
    __syncthreads();
    if (s_last != NBLOCKS - 1) return;

    // ---- final: sum(s^2), combine, write scalar, RE-ZERO accumulators
    float ssq = 0.0f;
    for (int e = threadIdx.x; e < 624; e += NTHREADS) {
        float v = g_s[e];
        ssq = fmaf(v, v, ssq);
        g_s[e] = 0.0f;                                // restore zero-invariant
    }
    #pragma unroll
    for (int o = 16; o; o >>= 1) ssq += __shfl_xor_sync(0xffffffffu, ssq, o);
    if (lane == 0) s_fin[wid] = ssq;
    __syncthreads();

    if (threadIdx.x == 0) {
        float st = 0.0f;
        #pragma unroll
        for (int ww = 0; ww < NWARPS; ww++) st += s_fin[ww];
        double sumsq_t = (double)g_acc[0];
        double usum_t  = (double)g_acc[1];
        double pair    = 4096.0 * sumsq_t - (double)st;
        double align   = pair / (8386560.0 * 39.0);        // n_pairs * F
        double uni     = usum_t / (4096.0 * 39.0 * 39.0);  // B * F * F
        out[0] = (float)((align + uni) * 0.01);            // * BETA
        g_acc[0] = 0.0f;
        g_acc[1] = 0.0f;
        g_count  = 0u;                                     // reset for next replay
    }
}

extern "C" void kernel_launch(void* const* d_in, const int* in_sizes, int n_in,
                              void* d_out, int out_size) {
    const int*   x   = (const int*)d_in[0];
    const float* emb = (const float*)d_in[1];
    cl4_fused<<<NBLOCKS, NTHREADS>>>(x, emb, (float*)d_out);
}